// round 16
// baseline (speedup 1.0000x reference)
#include <cuda_runtime.h>
#include <cuda_fp16.h>
#include <math.h>
#include <stdint.h>

#define DIM 768
#define BATCH 16
#define SEQ 1024
#define ROWS (BATCH*SEQ)   // 16384

// ---------------- scratch (module-load allocation, legal) ----------------
__device__ __half g_xA[(size_t)ROWS*DIM];      // A_perm16
__device__ __half g_xB[(size_t)ROWS*DIM];      // A_perm16
__device__ __half g_xC[(size_t)ROWS*DIM];      // A_perm16
__device__ __half g_Wq[(size_t)DIM*DIM];       // B_perm2
__device__ __half g_Wk[(size_t)DIM*DIM];       // B_perm2
__device__ __half g_Wv[(size_t)DIM*DIM];       // B_perm2
__device__ __half g_Wfc[(size_t)DIM*DIM];      // B_perm2
__device__ __half g_Q[(size_t)ROWS*DIM];       // A_perm16
__device__ __half g_KA[(size_t)ROWS*DIM];      // B_perm2 [seq,dim] per batch
__device__ __half g_KB[(size_t)ROWS*DIM];      // B_perm2
__device__ __half g_VA[(size_t)ROWS*DIM];      // B_perm2 [dim,seq] per batch
__device__ __half g_VB[(size_t)ROWS*DIM];      // B_perm2
__device__ __half g_h[(size_t)ROWS*DIM];       // A_perm16
__device__ __half g_scores1[(size_t)BATCH*SEQ*SEQ]; // A_perm16 per batch
__device__ __half g_scores2[(size_t)BATCH*SEQ*SEQ]; // A_perm16 per batch
__device__ __half g_interp[(size_t)ROWS*DIM];  // normal row-major fp16

// Fragment-major fp16 layouts (mma.m16n8k16.row.col):
// A_perm16: 16m x 16k blocks = 256 halves (512B). lane l=(g,c) holds uint4 A-frag.
// B_perm2:  8n x 32k blocks = 256 halves (512B). lane holds uint4 = two B-frags.

// ---------------- helpers ----------------
__device__ __forceinline__ void cp16(uint32_t d, const void* s) {
    asm volatile("cp.async.ca.shared.global [%0], [%1], 16;" :: "r"(d), "l"(s));
}
__device__ __forceinline__ void cpcommit() { asm volatile("cp.async.commit_group;"); }

__device__ __forceinline__ void mma_f16(float* c, const uint32_t* a, uint32_t b0, uint32_t b1) {
    asm("mma.sync.aligned.m16n8k16.row.col.f32.f16.f16.f32 "
        "{%0,%1,%2,%3}, {%4,%5,%6,%7}, {%8,%9}, {%0,%1,%2,%3};"
        : "+f"(c[0]), "+f"(c[1]), "+f"(c[2]), "+f"(c[3])
        : "r"(a[0]), "r"(a[1]), "r"(a[2]), "r"(a[3]), "r"(b0), "r"(b1));
}
__device__ __forceinline__ uint32_t packh2(float x, float y) {
    __half2 h = __floats2half2_rn(x, y);
    return *reinterpret_cast<uint32_t*>(&h);
}

// ---------------- prepass: pack fp32 -> fp16 fragment-major ----------------
__global__ __launch_bounds__(256)
void pack_A3(const float* __restrict__ s0, const float* __restrict__ s1,
             const float* __restrict__ s2)
{
    const int which = blockIdx.y;
    const float* src = which == 0 ? s0 : which == 1 ? s1 : s2;
    __half* dst = which == 0 ? g_xA : which == 1 ? g_xB : g_xC;
    int blk = blockIdx.x * 8 + (threadIdx.x >> 5);
    const int K16 = DIM >> 4;
    int mb = blk / K16, kb = blk % K16;
    int lane = threadIdx.x & 31;
    int g = lane >> 2, c = lane & 3;
    const float* s = src + (size_t)(mb * 16 + g) * DIM + kb * 16 + 2 * c;
    const float* s8 = s + (size_t)8 * DIM;
    uint4 v;
    v.x = packh2(s[0], s[1]);
    v.y = packh2(s8[0], s8[1]);
    v.z = packh2(s[8], s[9]);
    v.w = packh2(s8[8], s8[9]);
    reinterpret_cast<uint4*>(dst)[(size_t)blk * 32 + lane] = v;
}

__global__ __launch_bounds__(256)
void pack_B4(const float* __restrict__ s0, const float* __restrict__ s1,
             const float* __restrict__ s2, const float* __restrict__ s3)
{
    const int which = blockIdx.y;
    const float* src = which == 0 ? s0 : which == 1 ? s1 : which == 2 ? s2 : s3;
    __half* dst = which == 0 ? g_Wq : which == 1 ? g_Wk : which == 2 ? g_Wv : g_Wfc;
    int blk = blockIdx.x * 8 + (threadIdx.x >> 5);
    const int K32 = DIM >> 5;
    int nb = blk / K32, kb = blk % K32;
    int lane = threadIdx.x & 31;
    int g = lane >> 2, c = lane & 3;
    const float* s = src + (size_t)(nb * 8 + g) * DIM + kb * 32 + 2 * c;
    uint4 v;
    v.x = packh2(s[0], s[1]);
    v.y = packh2(s[8], s[9]);
    v.z = packh2(s[16], s[17]);
    v.w = packh2(s[24], s[25]);
    reinterpret_cast<uint4*>(dst)[(size_t)blk * 32 + lane] = v;
}

// ---------------- GEMM config: 6-stage ring, 1 barrier per 2 k-tiles ----------------
constexpr int BM = 128, BN = 128, BK = 32;
constexpr int STAGE_BYTES = 16384;                 // A 8KB + B 8KB
constexpr int NSTAGES = 6;
constexpr int SMEM_BYTES = NSTAGES * STAGE_BYTES;  // 98304 (2 CTAs -> 192KB <= 227KB)

// ---------------- merged projection GEMM: one launch for Q/K/V ----------------
__global__ __launch_bounds__(256, 2)
void proj_gemm(const __half* __restrict__ xA, const __half* __restrict__ xB,
               const __half* __restrict__ xC,
               const __half* __restrict__ Wq, const __half* __restrict__ Wk,
               const __half* __restrict__ Wv,
               const float* __restrict__ bq, const float* __restrict__ bk,
               const float* __restrict__ bv,
               __half* __restrict__ Q, __half* __restrict__ KA,
               __half* __restrict__ KB, __half* __restrict__ VA,
               __half* __restrict__ VB)
{
    extern __shared__ __align__(16) char smem[];

    const int z = blockIdx.z;
    const __half* A;
    const __half* B;
    const float* bias;
    __half* out;
    int wb;
    switch (z) {
        case 0:  A = xC; B = Wq; bias = bq; out = Q;  wb = 1; break;
        case 1:  A = xA; B = Wk; bias = bk; out = KA; wb = 2; break;
        case 2:  A = xB; B = Wk; bias = bk; out = KB; wb = 2; break;
        case 3:  A = xA; B = Wv; bias = bv; out = VA; wb = 3; break;
        default: A = xB; B = Wv; bias = bv; out = VB; wb = 3; break;
    }

    const int t    = threadIdx.x;
    const int lane = t & 31;
    const int warp = t >> 5;
    const int wm   = warp >> 1;
    const int wn   = warp & 1;
    const int g    = lane >> 2;
    const int c    = lane & 3;
    const int m0   = blockIdx.y * BM;
    const int n0   = blockIdx.x * BN;

    const uint32_t smBase = (uint32_t)__cvta_generic_to_shared(smem);
    const int K16 = DIM >> 4, K32 = DIM >> 5;
    const __half* Ab = A + (size_t)(m0 >> 4) * K16 * 256;
    const __half* Bb = B + (size_t)(n0 >> 3) * K32 * 256;

    float acc[2][8][4] = {};
    const int NT = DIM / BK;   // 24 (even)

    auto issue = [&](int kt) {
        const int st = kt % NSTAGES;
        uint32_t as = smBase + st * STAGE_BYTES;
        #pragma unroll
        for (int i = 0; i < 2; i++) {
            int idx = t + 256 * i;
            int bid = idx >> 5, rest = idx & 31;
            int mb = bid >> 1, kb = bid & 1;
            cp16(as + bid * 512 + rest * 16,
                 Ab + ((size_t)mb * K16 + kt * 2 + kb) * 256 + rest * 8);
        }
        uint32_t bs = as + 8192;
        #pragma unroll
        for (int i = 0; i < 2; i++) {
            int idx = t + 256 * i;
            int nb = idx >> 5, rest = idx & 31;
            cp16(bs + nb * 512 + rest * 16,
                 Bb + ((size_t)nb * K32 + kt) * 256 + rest * 8);
        }
        cpcommit();
    };

    auto compute = [&](int kt) {
        const int st = kt % NSTAGES;
        const char* sAc = smem + st * STAGE_BYTES;
        const char* sBc = sAc + 8192;
        uint4 af[2][2];
        #pragma unroll
        for (int mi = 0; mi < 2; mi++)
            #pragma unroll
            for (int kb = 0; kb < 2; kb++)
                af[mi][kb] = *reinterpret_cast<const uint4*>(
                    sAc + ((wm * 2 + mi) * 2 + kb) * 512 + lane * 16);
        #pragma unroll
        for (int hh = 0; hh < 2; hh++) {
            uint4 bq4[4];
            #pragma unroll
            for (int n4 = 0; n4 < 4; n4++)
                bq4[n4] = *reinterpret_cast<const uint4*>(
                    sBc + (wn * 8 + hh * 4 + n4) * 512 + lane * 16);
            #pragma unroll
            for (int mi = 0; mi < 2; mi++)
                #pragma unroll
                for (int n4 = 0; n4 < 4; n4++) {
                    const int ni = hh * 4 + n4;
                    mma_f16(acc[mi][ni],
                            reinterpret_cast<const uint32_t*>(&af[mi][0]),
                            bq4[n4].x, bq4[n4].y);
                    mma_f16(acc[mi][ni],
                            reinterpret_cast<const uint32_t*>(&af[mi][1]),
                            bq4[n4].z, bq4[n4].w);
                }
        }
    };

    issue(0); issue(1); issue(2); issue(3);

    for (int kt = 0; kt < NT; kt += 2) {
        if (kt + 3 < NT) asm volatile("cp.async.wait_group 2;");
        else             asm volatile("cp.async.wait_group 0;");
        __syncthreads();
        compute(kt);
        compute(kt + 1);
        if (kt + 4 < NT) issue(kt + 4);
        if (kt + 5 < NT) issue(kt + 5);
    }

    // ---------------- epilogue (runtime wb) ----------------
    #pragma unroll
    for (int mi = 0; mi < 2; mi++) {
        const int r0 = m0 + wm * 32 + mi * 16 + g;
        #pragma unroll
        for (int ni = 0; ni < 8; ni++) {
            const int col = n0 + wn * 64 + ni * 8 + 2 * c;
            float bx = bias[col], by = bias[col + 1];
            float v0 = acc[mi][ni][0] + bx;
            float v1 = acc[mi][ni][1] + by;
            float v2 = acc[mi][ni][2] + bx;
            float v3 = acc[mi][ni][3] + by;
            if (wb == 1) {
                uint32_t* base = (uint32_t*)out;
                size_t blk = (size_t)(r0 >> 4) * (DIM >> 4) + (col >> 4);
                size_t idx = blk * 128 + lane * 4 + 2 * (ni & 1);
                uint2 w;
                w.x = packh2(v0, v1);
                w.y = packh2(v2, v3);
                *reinterpret_cast<uint2*>(base + idx) = w;
            } else if (wb == 2) {
                uint32_t* base = (uint32_t*)out;
                const int Kp32 = DIM >> 5;
                size_t blk = (size_t)(r0 >> 3) * Kp32 + (col >> 5);
                size_t sub = (size_t)lane * 4 + ((ni >> 1) & 1) * 2 + (ni & 1);
                base[blk * 128 + sub] = packh2(v0, v1);
                base[(blk + Kp32) * 128 + sub] = packh2(v2, v3);
            } else {  // wb == 3: transposed per batch -> B_perm2 [dim, seq]
                const int b = r0 >> 10;
                __half* base = out + (size_t)b * SEQ * DIM;
                const int SK32 = SEQ >> 5;
                #pragma unroll
                for (int e = 0; e < 4; e++) {
                    int n = col + (e & 1);
                    int k = (r0 & 1023) + (e >> 1) * 8;
                    float vv = (e == 0) ? v0 : (e == 1) ? v1 : (e == 2) ? v2 : v3;
                    size_t off = ((size_t)(n >> 3) * SK32 + (k >> 5)) * 256
                               + ((size_t)((n & 7) * 4 + ((k & 7) >> 1))) * 8
                               + ((k >> 4) & 1) * 4 + ((k >> 3) & 1) * 2 + (k & 1);
                    base[off] = __float2half_rn(vv);
                }
            }
        }
    }
}

// ---------------- generic fp16 GEMM ----------------
// WB: 0 normal fp32 C; 1 A_perm16 half (Kp); 4 normal row-major half C.
template<int WB, bool HAS_BIAS, bool DUALK>
__global__ __launch_bounds__(256, 2)
void mma_gemm(const __half* __restrict__ Ag, const __half* __restrict__ Ag2,
              const __half* __restrict__ Bg, const __half* __restrict__ Bg2,
              const float* __restrict__ bias, void* __restrict__ Cg,
              void* __restrict__ Cg2, int zsplit,
              int N, int K, int Kp, long sA, long sB, long sC, float alpha)
{
    extern __shared__ __align__(16) char smem[];

    int z = blockIdx.z;
    const __half *A, *B, *A2 = nullptr, *B2 = nullptr;
    char* Cb;
    if (!DUALK && z >= zsplit) {
        int zz = z - zsplit;
        A = Ag2 + (size_t)zz * sA;
        B = Bg2 + (size_t)zz * sB;
        Cb = (char*)Cg2;
        z = zz;
    } else {
        A = Ag + (size_t)z * sA;
        B = Bg + (size_t)z * sB;
        Cb = (char*)Cg;
        if (DUALK) {
            A2 = Ag2 + (size_t)z * sA;
            B2 = Bg2 + (size_t)z * sB;
        }
    }

    const int t    = threadIdx.x;
    const int lane = t & 31;
    const int warp = t >> 5;
    const int wm   = warp >> 1;
    const int wn   = warp & 1;
    const int g    = lane >> 2;
    const int c    = lane & 3;
    const int m0   = blockIdx.y * BM;
    const int n0   = blockIdx.x * BN;

    const uint32_t smBase = (uint32_t)__cvta_generic_to_shared(smem);
    const int K16 = K >> 4, K32 = K >> 5;
    const __half* Ab1 = A + (size_t)(m0 >> 4) * K16 * 256;
    const __half* Bb1 = B + (size_t)(n0 >> 3) * K32 * 256;
    const __half* Ab2 = DUALK ? A2 + (size_t)(m0 >> 4) * K16 * 256 : nullptr;
    const __half* Bb2 = DUALK ? B2 + (size_t)(n0 >> 3) * K32 * 256 : nullptr;

    float acc[2][8][4] = {};
    const int nkt = K / BK;
    const int NT = DUALK ? 2 * nkt : nkt;   // always even

    auto issue = [&](int kt) {
        const int st = kt % NSTAGES;
        const bool sel = DUALK && (kt >= nkt);
        const int kk = sel ? kt - nkt : kt;
        const __half* Ab = sel ? Ab2 : Ab1;
        const __half* Bb = sel ? Bb2 : Bb1;
        uint32_t as = smBase + st * STAGE_BYTES;
        #pragma unroll
        for (int i = 0; i < 2; i++) {
            int idx = t + 256 * i;
            int bid = idx >> 5, rest = idx & 31;
            int mb = bid >> 1, kb = bid & 1;
            cp16(as + bid * 512 + rest * 16,
                 Ab + ((size_t)mb * K16 + kk * 2 + kb) * 256 + rest * 8);
        }
        uint32_t bs = as + 8192;
        #pragma unroll
        for (int i = 0; i < 2; i++) {
            int idx = t + 256 * i;
            int nb = idx >> 5, rest = idx & 31;
            cp16(bs + nb * 512 + rest * 16,
                 Bb + ((size_t)nb * K32 + kk) * 256 + rest * 8);
        }
        cpcommit();
    };

    auto compute = [&](int kt) {
        const int st = kt % NSTAGES;
        const char* sAc = smem + st * STAGE_BYTES;
        const char* sBc = sAc + 8192;
        uint4 af[2][2];
        #pragma unroll
        for (int mi = 0; mi < 2; mi++)
            #pragma unroll
            for (int kb = 0; kb < 2; kb++)
                af[mi][kb] = *reinterpret_cast<const uint4*>(
                    sAc + ((wm * 2 + mi) * 2 + kb) * 512 + lane * 16);
        #pragma unroll
        for (int hh = 0; hh < 2; hh++) {
            uint4 bq4[4];
            #pragma unroll
            for (int n4 = 0; n4 < 4; n4++)
                bq4[n4] = *reinterpret_cast<const uint4*>(
                    sBc + (wn * 8 + hh * 4 + n4) * 512 + lane * 16);
            #pragma unroll
            for (int mi = 0; mi < 2; mi++)
                #pragma unroll
                for (int n4 = 0; n4 < 4; n4++) {
                    const int ni = hh * 4 + n4;
                    mma_f16(acc[mi][ni],
                            reinterpret_cast<const uint32_t*>(&af[mi][0]),
                            bq4[n4].x, bq4[n4].y);
                    mma_f16(acc[mi][ni],
                            reinterpret_cast<const uint32_t*>(&af[mi][1]),
                            bq4[n4].z, bq4[n4].w);
                }
        }
    };

    issue(0); issue(1); issue(2); issue(3);

    for (int kt = 0; kt < NT; kt += 2) {
        if (kt + 3 < NT) asm volatile("cp.async.wait_group 2;");
        else             asm volatile("cp.async.wait_group 0;");
        __syncthreads();
        compute(kt);
        compute(kt + 1);
        if (kt + 4 < NT) issue(kt + 4);
        if (kt + 5 < NT) issue(kt + 5);
    }

    // ---------------- epilogue ----------------
    #pragma unroll
    for (int mi = 0; mi < 2; mi++) {
        const int r0 = m0 + wm * 32 + mi * 16 + g;
        #pragma unroll
        for (int ni = 0; ni < 8; ni++) {
            const int col = n0 + wn * 64 + ni * 8 + 2 * c;
            float v0 = alpha * acc[mi][ni][0];
            float v1 = alpha * acc[mi][ni][1];
            float v2 = alpha * acc[mi][ni][2];
            float v3 = alpha * acc[mi][ni][3];
            if (HAS_BIAS) {
                float bx = bias[col], by = bias[col + 1];
                v0 += bx; v1 += by; v2 += bx; v3 += by;
            }
            if (WB == 0) {
                float* base = (float*)Cb + (size_t)z * sC;
                float* p0 = base + (size_t)r0 * N + col;
                float* p1 = p0 + (size_t)8 * N;
                float2 a0v, a1v;
                a0v.x = v0; a0v.y = v1; a1v.x = v2; a1v.y = v3;
                *reinterpret_cast<float2*>(p0) = a0v;
                *reinterpret_cast<float2*>(p1) = a1v;
            } else if (WB == 1) {
                uint32_t* base = (uint32_t*)((__half*)Cb + (size_t)z * sC);
                size_t blk = (size_t)(r0 >> 4) * (Kp >> 4) + (col >> 4);
                size_t idx = blk * 128 + lane * 4 + 2 * (ni & 1);
                uint2 w;
                w.x = packh2(v0, v1);
                w.y = packh2(v2, v3);
                *reinterpret_cast<uint2*>(base + idx) = w;
            } else {  // WB == 4: normal row-major half
                __half* base = (__half*)Cb + (size_t)z * sC;
                *reinterpret_cast<uint32_t*>(base + (size_t)r0 * N + col) = packh2(v0, v1);
                *reinterpret_cast<uint32_t*>(base + (size_t)(r0 + 8) * N + col) = packh2(v2, v3);
            }
        }
    }
}

// ---------- softmax on A_perm16 half scores; one block per row-pair (m, m+8) ----------
__global__ __launch_bounds__(256)
void softmax_perm(__half* __restrict__ S1, __half* __restrict__ S2)
{
    __shared__ float sh0[8], sh1[8];
    const int bid = blockIdx.x & 8191;
    __half* S = (blockIdx.x >> 13) ? S2 : S1;
    const int g = bid & 7, mh = (bid >> 3) & 63, b = bid >> 9;
    uint32_t* base = (uint32_t*)S + (size_t)b * (SEQ * SEQ / 2) + (size_t)mh * 8192 + g * 16;
    const int t = threadIdx.x;
    const int lane = t & 31, wid = t >> 5;
    const int kb = t >> 2, c = t & 3;

    uint4* p = reinterpret_cast<uint4*>(base + (size_t)kb * 128 + c * 4);
    uint4 u = *p;
    float2 f0 = __half22float2(*reinterpret_cast<__half2*>(&u.x));
    float2 f1 = __half22float2(*reinterpret_cast<__half2*>(&u.y));
    float2 f2 = __half22float2(*reinterpret_cast<__half2*>(&u.z));
    float2 f3 = __half22float2(*reinterpret_cast<__half2*>(&u.w));

    float m0v = fmaxf(fmaxf(f0.x, f0.y), fmaxf(f2.x, f2.y));
    float m1v = fmaxf(fmaxf(f1.x, f1.y), fmaxf(f3.x, f3.y));
    #pragma unroll
    for (int o = 16; o > 0; o >>= 1) {
        m0v = fmaxf(m0v, __shfl_xor_sync(0xffffffffu, m0v, o));
        m1v = fmaxf(m1v, __shfl_xor_sync(0xffffffffu, m1v, o));
    }
    if (lane == 0) { sh0[wid] = m0v; sh1[wid] = m1v; }
    __syncthreads();
    m0v = sh0[0]; m1v = sh1[0];
    #pragma unroll
    for (int i = 1; i < 8; i++) { m0v = fmaxf(m0v, sh0[i]); m1v = fmaxf(m1v, sh1[i]); }
    __syncthreads();

    const float L2E = 1.4426950408889634f;
    __half2 e0 = h2exp2(__floats2half2_rn((f0.x - m0v) * L2E, (f0.y - m0v) * L2E));
    __half2 e2 = h2exp2(__floats2half2_rn((f2.x - m0v) * L2E, (f2.y - m0v) * L2E));
    __half2 e1 = h2exp2(__floats2half2_rn((f1.x - m1v) * L2E, (f1.y - m1v) * L2E));
    __half2 e3 = h2exp2(__floats2half2_rn((f3.x - m1v) * L2E, (f3.y - m1v) * L2E));
    float2 g0 = __half22float2(e0), g1 = __half22float2(e1);
    float2 g2 = __half22float2(e2), g3 = __half22float2(e3);

    float s0 = g0.x + g0.y + g2.x + g2.y;
    float s1 = g1.x + g1.y + g3.x + g3.y;
    #pragma unroll
    for (int o = 16; o > 0; o >>= 1) {
        s0 += __shfl_xor_sync(0xffffffffu, s0, o);
        s1 += __shfl_xor_sync(0xffffffffu, s1, o);
    }
    if (lane == 0) { sh0[wid] = s0; sh1[wid] = s1; }
    __syncthreads();
    s0 = sh0[0]; s1 = sh1[0];
    #pragma unroll
    for (int i = 1; i < 8; i++) { s0 += sh0[i]; s1 += sh1[i]; }

    const float i0 = 1.0f / s0, i1 = 1.0f / s1;
    u.x = packh2(g0.x * i0, g0.y * i0);
    u.z = packh2(g2.x * i0, g2.y * i0);
    u.y = packh2(g1.x * i1, g1.y * i1);
    u.w = packh2(g3.x * i1, g3.y * i1);
    *p = u;
}

// ------------- fused residual-add + LayerNorm; writes h in A_perm16 half -------------
__global__ __launch_bounds__(256)
void ln_kernel(const __half* __restrict__ interp, const float* __restrict__ xC,
               const float* __restrict__ gamma, const float* __restrict__ beta,
               __half* __restrict__ H)
{
    __shared__ float sh[8];
    const size_t row = blockIdx.x;
    const __half* a = interp + row * DIM;
    const float* cc = xC + row * DIM;
    const int t = threadIdx.x;

    float x0 = __half2float(a[t])       + cc[t];
    float x1 = __half2float(a[t + 256]) + cc[t + 256];
    float x2 = __half2float(a[t + 512]) + cc[t + 512];

    float s = x0 + x1 + x2;
    #pragma unroll
    for (int o = 16; o > 0; o >>= 1) s += __shfl_xor_sync(0xffffffffu, s, o);
    if ((t & 31) == 0) sh[t >> 5] = s;
    __syncthreads();
    s = sh[0];
    #pragma unroll
    for (int i = 1; i < 8; i++) s += sh[i];
    const float mu = s * (1.0f / DIM);
    __syncthreads();

    float d0 = x0 - mu, d1 = x1 - mu, d2 = x2 - mu;
    float q = d0 * d0 + d1 * d1 + d2 * d2;
    #pragma unroll
    for (int o = 16; o > 0; o >>= 1) q += __shfl_xor_sync(0xffffffffu, q, o);
    if ((t & 31) == 0) sh[t >> 5] = q;
    __syncthreads();
    q = sh[0];
    #pragma unroll
    for (int i = 1; i < 8; i++) q += sh[i];

    const float rstd = rsqrtf(q * (1.0f / DIM) + 1e-5f);
    const int m = (int)row;
    const size_t rowblk = (size_t)(m >> 4) * (DIM >> 4);
    const int laneb = (m & 7) * 4;
    const int regm = (m >> 3) & 1;
    #pragma unroll
    for (int i = 0; i < 3; i++) {
        int d = t + i * 256;
        float val = (i == 0 ? d0 : i == 1 ? d1 : d2) * rstd * gamma[d] + beta[d];
        size_t off = (rowblk + (d >> 4)) * 256
                   + (size_t)(laneb + ((d & 7) >> 1)) * 8
                   + (regm + 2 * ((d & 15) >> 3)) * 2 + (d & 1);
        H[off] = __float2half_rn(val);
    }
}

// ---------------------------------- launch ----------------------------------
extern "C" void kernel_launch(void* const* d_in, const int* in_sizes, int n_in,
                              void* d_out, int out_size)
{
    const float* xA    = (const float*)d_in[0];
    const float* xB    = (const float*)d_in[1];
    const float* xC    = (const float*)d_in[2];
    const float* Wq    = (const float*)d_in[3];
    const float* bq    = (const float*)d_in[4];
    const float* Wk    = (const float*)d_in[5];
    const float* bk    = (const float*)d_in[6];
    const float* Wv    = (const float*)d_in[7];
    const float* bv    = (const float*)d_in[8];
    const float* gamma = (const float*)d_in[9];
    const float* beta  = (const float*)d_in[10];
    const float* Wfc   = (const float*)d_in[11];
    const float* bfc   = (const float*)d_in[12];
    float* out = (float*)d_out;

    __half *pxA, *pxB, *pxC, *pWq, *pWk, *pWv, *pWfc;
    __half *Q, *KA, *KB, *VA, *VB, *h, *sc1, *sc2, *interp;
    cudaGetSymbolAddress((void**)&pxA,  g_xA);
    cudaGetSymbolAddress((void**)&pxB,  g_xB);
    cudaGetSymbolAddress((void**)&pxC,  g_xC);
    cudaGetSymbolAddress((void**)&pWq,  g_Wq);
    cudaGetSymbolAddress((void**)&pWk,  g_Wk);
    cudaGetSymbolAddress((void**)&pWv,  g_Wv);
    cudaGetSymbolAddress((void**)&pWfc, g_Wfc);
    cudaGetSymbolAddress((void**)&Q,      g_Q);
    cudaGetSymbolAddress((void**)&KA,     g_KA);
    cudaGetSymbolAddress((void**)&KB,     g_KB);
    cudaGetSymbolAddress((void**)&VA,     g_VA);
    cudaGetSymbolAddress((void**)&VB,     g_VB);
    cudaGetSymbolAddress((void**)&h,      g_h);
    cudaGetSymbolAddress((void**)&sc1,    g_scores1);
    cudaGetSymbolAddress((void**)&sc2,    g_scores2);
    cudaGetSymbolAddress((void**)&interp, g_interp);

    cudaFuncSetAttribute(proj_gemm,                 cudaFuncAttributeMaxDynamicSharedMemorySize, SMEM_BYTES);
    cudaFuncSetAttribute(mma_gemm<1, false, false>, cudaFuncAttributeMaxDynamicSharedMemorySize, SMEM_BYTES);
    cudaFuncSetAttribute(mma_gemm<4, false, true >, cudaFuncAttributeMaxDynamicSharedMemorySize, SMEM_BYTES);
    cudaFuncSetAttribute(mma_gemm<0, true,  false>, cudaFuncAttributeMaxDynamicSharedMemorySize, SMEM_BYTES);

    const long sQK = (long)SEQ * DIM;    // halves
    const long sS  = (long)SEQ * SEQ;    // halves
    const float scale = 1.0f / sqrtf((float)DIM);
    const int ZBIG = 1 << 30;

    // prepass: pack fp32 -> fp16 fragment layouts
    {
        int nblkA = (ROWS >> 4) * (DIM >> 4);
        pack_A3<<<dim3(nblkA / 8, 3, 1), 256>>>(xA, xB, xC);
        int nblkB = (DIM >> 3) * (DIM >> 5);
        pack_B4<<<dim3(nblkB / 8, 4, 1), 256>>>(Wq, Wk, Wv, Wfc);
    }

    const dim3 blk(256);

    // ALL projections in one launch (z = 0..4): Q, KA, KB, VA, VB
    proj_gemm<<<dim3(DIM/BN, ROWS/BM, 5), blk, SMEM_BYTES>>>(
        pxA, pxB, pxC, pWq, pWk, pWv, bq, bk, bv, Q, KA, KB, VA, VB);

    // scores merged: z<16: Q@KA^T -> sc1 ; z>=16: Q@KB^T -> sc2 (A_perm16 out)
    mma_gemm<1, false, false><<<dim3(SEQ/BN, SEQ/BM, 32), blk, SMEM_BYTES>>>(
        Q, Q, KA, KB, nullptr, sc1, sc2, 16,
        SEQ, DIM, SEQ, sQK, sQK, sS, scale);

    // softmax (both buffers), f16x2 exp
    softmax_perm<<<BATCH * 512 * 2, 256>>>(sc1, sc2);

    // PV dual-K: interp = sc1@VA^T + sc2@VB^T (half row-major)
    mma_gemm<4, false, true><<<dim3(DIM/BN, SEQ/BM, BATCH), blk, SMEM_BYTES>>>(
        sc1, sc2, VA, VB, nullptr, interp, nullptr, ZBIG,
        DIM, SEQ, 0, sS, sQK, sQK, 1.0f);

    // residual + LN -> h (A_perm16)
    ln_kernel<<<ROWS, blk>>>(interp, xC, gamma, beta, h);

    // FC: h @ Wfc^T + bfc -> out (fp32)
    mma_gemm<0, true, false><<<dim3(DIM/BN, ROWS/BM, 1), blk, SMEM_BYTES>>>(
        h, nullptr, pWfc, nullptr, bfc, out, nullptr, ZBIG,
        DIM, DIM, 0, 0, 0, 0, 1.0f);
}

// round 17
// speedup vs baseline: 1.5729x; 1.5729x over previous
#include <cuda_runtime.h>
#include <cuda_fp16.h>
#include <math.h>
#include <stdint.h>

#define DIM 768
#define BATCH 16
#define SEQ 1024
#define ROWS (BATCH*SEQ)   // 16384

// ---------------- scratch (module-load allocation, legal) ----------------
__device__ __half g_xA[(size_t)ROWS*DIM];      // A_perm16
__device__ __half g_xB[(size_t)ROWS*DIM];      // A_perm16
__device__ __half g_xC[(size_t)ROWS*DIM];      // A_perm16
__device__ __half g_Wq[(size_t)DIM*DIM];       // B_perm2
__device__ __half g_Wk[(size_t)DIM*DIM];       // B_perm2
__device__ __half g_Wv[(size_t)DIM*DIM];       // B_perm2
__device__ __half g_Wfc[(size_t)DIM*DIM];      // B_perm2
__device__ __half g_Q[(size_t)ROWS*DIM];       // A_perm16
__device__ __half g_KA[(size_t)ROWS*DIM];      // B_perm2 [seq,dim] per batch
__device__ __half g_KB[(size_t)ROWS*DIM];      // B_perm2
__device__ __half g_VA[(size_t)ROWS*DIM];      // B_perm2 [dim,seq] per batch
__device__ __half g_VB[(size_t)ROWS*DIM];      // B_perm2
__device__ __half g_h[(size_t)ROWS*DIM];       // A_perm16
__device__ __half g_scores1[(size_t)BATCH*SEQ*SEQ]; // A_perm16 per batch
__device__ __half g_scores2[(size_t)BATCH*SEQ*SEQ]; // A_perm16 per batch
__device__ __half g_interp[(size_t)ROWS*DIM];  // normal row-major fp16

// Fragment-major fp16 layouts (mma.m16n8k16.row.col):
// A_perm16: 16m x 16k blocks = 256 halves (512B). lane l=(g,c) holds uint4 A-frag.
// B_perm2:  8n x 32k blocks = 256 halves (512B). lane holds uint4 = two B-frags.

// ---------------- helpers ----------------
__device__ __forceinline__ void cp16(uint32_t d, const void* s) {
    asm volatile("cp.async.ca.shared.global [%0], [%1], 16;" :: "r"(d), "l"(s));
}
__device__ __forceinline__ void cpcommit() { asm volatile("cp.async.commit_group;"); }

__device__ __forceinline__ void mma_f16(float* c, const uint32_t* a, uint32_t b0, uint32_t b1) {
    asm("mma.sync.aligned.m16n8k16.row.col.f32.f16.f16.f32 "
        "{%0,%1,%2,%3}, {%4,%5,%6,%7}, {%8,%9}, {%0,%1,%2,%3};"
        : "+f"(c[0]), "+f"(c[1]), "+f"(c[2]), "+f"(c[3])
        : "r"(a[0]), "r"(a[1]), "r"(a[2]), "r"(a[3]), "r"(b0), "r"(b1));
}
__device__ __forceinline__ uint32_t packh2(float x, float y) {
    __half2 h = __floats2half2_rn(x, y);
    return *reinterpret_cast<uint32_t*>(&h);
}

// ---------------- prepass: pack fp32 -> fp16 fragment-major ----------------
__global__ __launch_bounds__(256)
void pack_A3(const float* __restrict__ s0, const float* __restrict__ s1,
             const float* __restrict__ s2)
{
    const int which = blockIdx.y;
    const float* src = which == 0 ? s0 : which == 1 ? s1 : s2;
    __half* dst = which == 0 ? g_xA : which == 1 ? g_xB : g_xC;
    int blk = blockIdx.x * 8 + (threadIdx.x >> 5);
    const int K16 = DIM >> 4;
    int mb = blk / K16, kb = blk % K16;
    int lane = threadIdx.x & 31;
    int g = lane >> 2, c = lane & 3;
    const float* s = src + (size_t)(mb * 16 + g) * DIM + kb * 16 + 2 * c;
    const float* s8 = s + (size_t)8 * DIM;
    uint4 v;
    v.x = packh2(s[0], s[1]);
    v.y = packh2(s8[0], s8[1]);
    v.z = packh2(s[8], s[9]);
    v.w = packh2(s8[8], s8[9]);
    reinterpret_cast<uint4*>(dst)[(size_t)blk * 32 + lane] = v;
}

__global__ __launch_bounds__(256)
void pack_B4(const float* __restrict__ s0, const float* __restrict__ s1,
             const float* __restrict__ s2, const float* __restrict__ s3)
{
    const int which = blockIdx.y;
    const float* src = which == 0 ? s0 : which == 1 ? s1 : which == 2 ? s2 : s3;
    __half* dst = which == 0 ? g_Wq : which == 1 ? g_Wk : which == 2 ? g_Wv : g_Wfc;
    int blk = blockIdx.x * 8 + (threadIdx.x >> 5);
    const int K32 = DIM >> 5;
    int nb = blk / K32, kb = blk % K32;
    int lane = threadIdx.x & 31;
    int g = lane >> 2, c = lane & 3;
    const float* s = src + (size_t)(nb * 8 + g) * DIM + kb * 32 + 2 * c;
    uint4 v;
    v.x = packh2(s[0], s[1]);
    v.y = packh2(s[8], s[9]);
    v.z = packh2(s[16], s[17]);
    v.w = packh2(s[24], s[25]);
    reinterpret_cast<uint4*>(dst)[(size_t)blk * 32 + lane] = v;
}

// ---------------- GEMM config (R15 proven structure): 4-stage ring ----------------
constexpr int BM = 128, BN = 128, BK = 32;
constexpr int STAGE_BYTES = 16384;                 // A 8KB + B 8KB
constexpr int SMEM_BYTES = 4 * STAGE_BYTES;        // 65536

// ---------------- merged projection GEMM: one launch for Q/K/V ----------------
__global__ __launch_bounds__(256, 2)
void proj_gemm(const __half* __restrict__ xA, const __half* __restrict__ xB,
               const __half* __restrict__ xC,
               const __half* __restrict__ Wq, const __half* __restrict__ Wk,
               const __half* __restrict__ Wv,
               const float* __restrict__ bq, const float* __restrict__ bk,
               const float* __restrict__ bv,
               __half* __restrict__ Q, __half* __restrict__ KA,
               __half* __restrict__ KB, __half* __restrict__ VA,
               __half* __restrict__ VB)
{
    extern __shared__ __align__(16) char smem[];

    const int z = blockIdx.z;
    const __half* A;
    const __half* B;
    const float* bias;
    __half* out;
    int wb;
    switch (z) {
        case 0:  A = xC; B = Wq; bias = bq; out = Q;  wb = 1; break;
        case 1:  A = xA; B = Wk; bias = bk; out = KA; wb = 2; break;
        case 2:  A = xB; B = Wk; bias = bk; out = KB; wb = 2; break;
        case 3:  A = xA; B = Wv; bias = bv; out = VA; wb = 3; break;
        default: A = xB; B = Wv; bias = bv; out = VB; wb = 3; break;
    }

    const int t    = threadIdx.x;
    const int lane = t & 31;
    const int warp = t >> 5;
    const int wm   = warp >> 1;
    const int wn   = warp & 1;
    const int g    = lane >> 2;
    const int c    = lane & 3;
    const int m0   = blockIdx.y * BM;
    const int n0   = blockIdx.x * BN;

    const uint32_t smBase = (uint32_t)__cvta_generic_to_shared(smem);
    const int K16 = DIM >> 4, K32 = DIM >> 5;
    const __half* Ab = A + (size_t)(m0 >> 4) * K16 * 256;
    const __half* Bb = B + (size_t)(n0 >> 3) * K32 * 256;

    float acc[2][8][4] = {};
    const int NT = DIM / BK;   // 24

    auto issue = [&](int kt) {
        const int st = kt & 3;
        uint32_t as = smBase + st * STAGE_BYTES;
        #pragma unroll
        for (int i = 0; i < 2; i++) {
            int idx = t + 256 * i;
            int bid = idx >> 5, rest = idx & 31;
            int mb = bid >> 1, kb = bid & 1;
            cp16(as + bid * 512 + rest * 16,
                 Ab + ((size_t)mb * K16 + kt * 2 + kb) * 256 + rest * 8);
        }
        uint32_t bs = as + 8192;
        #pragma unroll
        for (int i = 0; i < 2; i++) {
            int idx = t + 256 * i;
            int nb = idx >> 5, rest = idx & 31;
            cp16(bs + nb * 512 + rest * 16,
                 Bb + ((size_t)nb * K32 + kt) * 256 + rest * 8);
        }
        cpcommit();
    };

    issue(0);
    issue(1);
    issue(2);

    for (int kt = 0; kt < NT; kt++) {
        const int rem = NT - 1 - kt;
        if (rem >= 2)      asm volatile("cp.async.wait_group 2;");
        else if (rem == 1) asm volatile("cp.async.wait_group 1;");
        else               asm volatile("cp.async.wait_group 0;");
        __syncthreads();

        const int st = kt & 3;
        const char* sAc = smem + st * STAGE_BYTES;
        const char* sBc = sAc + 8192;

        uint4 af[2][2];
        #pragma unroll
        for (int mi = 0; mi < 2; mi++)
            #pragma unroll
            for (int kb = 0; kb < 2; kb++)
                af[mi][kb] = *reinterpret_cast<const uint4*>(
                    sAc + ((wm * 2 + mi) * 2 + kb) * 512 + lane * 16);

        #pragma unroll
        for (int hh = 0; hh < 2; hh++) {
            uint4 bq4[4];
            #pragma unroll
            for (int n4 = 0; n4 < 4; n4++)
                bq4[n4] = *reinterpret_cast<const uint4*>(
                    sBc + (wn * 8 + hh * 4 + n4) * 512 + lane * 16);
            #pragma unroll
            for (int mi = 0; mi < 2; mi++)
                #pragma unroll
                for (int n4 = 0; n4 < 4; n4++) {
                    const int ni = hh * 4 + n4;
                    mma_f16(acc[mi][ni],
                            reinterpret_cast<const uint32_t*>(&af[mi][0]),
                            bq4[n4].x, bq4[n4].y);
                    mma_f16(acc[mi][ni],
                            reinterpret_cast<const uint32_t*>(&af[mi][1]),
                            bq4[n4].z, bq4[n4].w);
                }
        }

        if (kt + 3 < NT) issue(kt + 3);
    }

    // ---------------- epilogue (runtime wb) ----------------
    #pragma unroll
    for (int mi = 0; mi < 2; mi++) {
        const int r0 = m0 + wm * 32 + mi * 16 + g;
        #pragma unroll
        for (int ni = 0; ni < 8; ni++) {
            const int col = n0 + wn * 64 + ni * 8 + 2 * c;
            float bx = bias[col], by = bias[col + 1];
            float v0 = acc[mi][ni][0] + bx;
            float v1 = acc[mi][ni][1] + by;
            float v2 = acc[mi][ni][2] + bx;
            float v3 = acc[mi][ni][3] + by;
            if (wb == 1) {
                uint32_t* base = (uint32_t*)out;
                size_t blk = (size_t)(r0 >> 4) * (DIM >> 4) + (col >> 4);
                size_t idx = blk * 128 + lane * 4 + 2 * (ni & 1);
                uint2 w;
                w.x = packh2(v0, v1);
                w.y = packh2(v2, v3);
                *reinterpret_cast<uint2*>(base + idx) = w;
            } else if (wb == 2) {
                uint32_t* base = (uint32_t*)out;
                const int Kp32 = DIM >> 5;
                size_t blk = (size_t)(r0 >> 3) * Kp32 + (col >> 5);
                size_t sub = (size_t)lane * 4 + ((ni >> 1) & 1) * 2 + (ni & 1);
                base[blk * 128 + sub] = packh2(v0, v1);
                base[(blk + Kp32) * 128 + sub] = packh2(v2, v3);
            } else {  // wb == 3: transposed per batch -> B_perm2 [dim, seq]
                const int b = r0 >> 10;
                __half* base = out + (size_t)b * SEQ * DIM;
                const int SK32 = SEQ >> 5;
                #pragma unroll
                for (int e = 0; e < 4; e++) {
                    int n = col + (e & 1);
                    int k = (r0 & 1023) + (e >> 1) * 8;
                    float vv = (e == 0) ? v0 : (e == 1) ? v1 : (e == 2) ? v2 : v3;
                    size_t off = ((size_t)(n >> 3) * SK32 + (k >> 5)) * 256
                               + ((size_t)((n & 7) * 4 + ((k & 7) >> 1))) * 8
                               + ((k >> 4) & 1) * 4 + ((k >> 3) & 1) * 2 + (k & 1);
                    base[off] = __float2half_rn(vv);
                }
            }
        }
    }
}

// ---------------- generic fp16 GEMM (R15 structure) ----------------
// WB: 0 normal fp32 C; 1 A_perm16 half (Kp); 4 normal row-major half C.
template<int WB, bool HAS_BIAS, bool DUALK>
__global__ __launch_bounds__(256, 2)
void mma_gemm(const __half* __restrict__ Ag, const __half* __restrict__ Ag2,
              const __half* __restrict__ Bg, const __half* __restrict__ Bg2,
              const float* __restrict__ bias, void* __restrict__ Cg,
              void* __restrict__ Cg2, int zsplit,
              int N, int K, int Kp, long sA, long sB, long sC, float alpha)
{
    extern __shared__ __align__(16) char smem[];

    int z = blockIdx.z;
    const __half *A, *B, *A2 = nullptr, *B2 = nullptr;
    char* Cb;
    if (!DUALK && z >= zsplit) {
        int zz = z - zsplit;
        A = Ag2 + (size_t)zz * sA;
        B = Bg2 + (size_t)zz * sB;
        Cb = (char*)Cg2;
        z = zz;
    } else {
        A = Ag + (size_t)z * sA;
        B = Bg + (size_t)z * sB;
        Cb = (char*)Cg;
        if (DUALK) {
            A2 = Ag2 + (size_t)z * sA;
            B2 = Bg2 + (size_t)z * sB;
        }
    }

    const int t    = threadIdx.x;
    const int lane = t & 31;
    const int warp = t >> 5;
    const int wm   = warp >> 1;
    const int wn   = warp & 1;
    const int g    = lane >> 2;
    const int c    = lane & 3;
    const int m0   = blockIdx.y * BM;
    const int n0   = blockIdx.x * BN;

    const uint32_t smBase = (uint32_t)__cvta_generic_to_shared(smem);
    const int K16 = K >> 4, K32 = K >> 5;
    const __half* Ab1 = A + (size_t)(m0 >> 4) * K16 * 256;
    const __half* Bb1 = B + (size_t)(n0 >> 3) * K32 * 256;
    const __half* Ab2 = DUALK ? A2 + (size_t)(m0 >> 4) * K16 * 256 : nullptr;
    const __half* Bb2 = DUALK ? B2 + (size_t)(n0 >> 3) * K32 * 256 : nullptr;

    float acc[2][8][4] = {};
    const int nkt = K / BK;
    const int NT = DUALK ? 2 * nkt : nkt;

    auto issue = [&](int kt) {
        const int st = kt & 3;
        const bool sel = DUALK && (kt >= nkt);
        const int kk = sel ? kt - nkt : kt;
        const __half* Ab = sel ? Ab2 : Ab1;
        const __half* Bb = sel ? Bb2 : Bb1;
        uint32_t as = smBase + st * STAGE_BYTES;
        #pragma unroll
        for (int i = 0; i < 2; i++) {
            int idx = t + 256 * i;
            int bid = idx >> 5, rest = idx & 31;
            int mb = bid >> 1, kb = bid & 1;
            cp16(as + bid * 512 + rest * 16,
                 Ab + ((size_t)mb * K16 + kk * 2 + kb) * 256 + rest * 8);
        }
        uint32_t bs = as + 8192;
        #pragma unroll
        for (int i = 0; i < 2; i++) {
            int idx = t + 256 * i;
            int nb = idx >> 5, rest = idx & 31;
            cp16(bs + nb * 512 + rest * 16,
                 Bb + ((size_t)nb * K32 + kk) * 256 + rest * 8);
        }
        cpcommit();
    };

    issue(0);
    if (NT > 1) issue(1);
    if (NT > 2) issue(2);

    for (int kt = 0; kt < NT; kt++) {
        const int rem = NT - 1 - kt;
        if (rem >= 2)      asm volatile("cp.async.wait_group 2;");
        else if (rem == 1) asm volatile("cp.async.wait_group 1;");
        else               asm volatile("cp.async.wait_group 0;");
        __syncthreads();

        const int st = kt & 3;
        const char* sAc = smem + st * STAGE_BYTES;
        const char* sBc = sAc + 8192;

        uint4 af[2][2];
        #pragma unroll
        for (int mi = 0; mi < 2; mi++)
            #pragma unroll
            for (int kb = 0; kb < 2; kb++)
                af[mi][kb] = *reinterpret_cast<const uint4*>(
                    sAc + ((wm * 2 + mi) * 2 + kb) * 512 + lane * 16);

        #pragma unroll
        for (int hh = 0; hh < 2; hh++) {
            uint4 bq4[4];
            #pragma unroll
            for (int n4 = 0; n4 < 4; n4++)
                bq4[n4] = *reinterpret_cast<const uint4*>(
                    sBc + (wn * 8 + hh * 4 + n4) * 512 + lane * 16);
            #pragma unroll
            for (int mi = 0; mi < 2; mi++)
                #pragma unroll
                for (int n4 = 0; n4 < 4; n4++) {
                    const int ni = hh * 4 + n4;
                    mma_f16(acc[mi][ni],
                            reinterpret_cast<const uint32_t*>(&af[mi][0]),
                            bq4[n4].x, bq4[n4].y);
                    mma_f16(acc[mi][ni],
                            reinterpret_cast<const uint32_t*>(&af[mi][1]),
                            bq4[n4].z, bq4[n4].w);
                }
        }

        if (kt + 3 < NT) issue(kt + 3);
    }

    // ---------------- epilogue ----------------
    #pragma unroll
    for (int mi = 0; mi < 2; mi++) {
        const int r0 = m0 + wm * 32 + mi * 16 + g;
        #pragma unroll
        for (int ni = 0; ni < 8; ni++) {
            const int col = n0 + wn * 64 + ni * 8 + 2 * c;
            float v0 = alpha * acc[mi][ni][0];
            float v1 = alpha * acc[mi][ni][1];
            float v2 = alpha * acc[mi][ni][2];
            float v3 = alpha * acc[mi][ni][3];
            if (HAS_BIAS) {
                float bx = bias[col], by = bias[col + 1];
                v0 += bx; v1 += by; v2 += bx; v3 += by;
            }
            if (WB == 0) {
                float* base = (float*)Cb + (size_t)z * sC;
                float* p0 = base + (size_t)r0 * N + col;
                float* p1 = p0 + (size_t)8 * N;
                float2 a0v, a1v;
                a0v.x = v0; a0v.y = v1; a1v.x = v2; a1v.y = v3;
                *reinterpret_cast<float2*>(p0) = a0v;
                *reinterpret_cast<float2*>(p1) = a1v;
            } else if (WB == 1) {
                uint32_t* base = (uint32_t*)((__half*)Cb + (size_t)z * sC);
                size_t blk = (size_t)(r0 >> 4) * (Kp >> 4) + (col >> 4);
                size_t idx = blk * 128 + lane * 4 + 2 * (ni & 1);
                uint2 w;
                w.x = packh2(v0, v1);
                w.y = packh2(v2, v3);
                *reinterpret_cast<uint2*>(base + idx) = w;
            } else {  // WB == 4: normal row-major half
                __half* base = (__half*)Cb + (size_t)z * sC;
                *reinterpret_cast<uint32_t*>(base + (size_t)r0 * N + col) = packh2(v0, v1);
                *reinterpret_cast<uint32_t*>(base + (size_t)(r0 + 8) * N + col) = packh2(v2, v3);
            }
        }
    }
}

// ---------- softmax on A_perm16 half scores; one block per row-pair (m, m+8) ----------
__global__ __launch_bounds__(256)
void softmax_perm(__half* __restrict__ S1, __half* __restrict__ S2)
{
    __shared__ float sh0[8], sh1[8];
    const int bid = blockIdx.x & 8191;
    __half* S = (blockIdx.x >> 13) ? S2 : S1;
    const int g = bid & 7, mh = (bid >> 3) & 63, b = bid >> 9;
    uint32_t* base = (uint32_t*)S + (size_t)b * (SEQ * SEQ / 2) + (size_t)mh * 8192 + g * 16;
    const int t = threadIdx.x;
    const int lane = t & 31, wid = t >> 5;
    const int kb = t >> 2, c = t & 3;

    uint4* p = reinterpret_cast<uint4*>(base + (size_t)kb * 128 + c * 4);
    uint4 u = *p;
    float2 f0 = __half22float2(*reinterpret_cast<__half2*>(&u.x));
    float2 f1 = __half22float2(*reinterpret_cast<__half2*>(&u.y));
    float2 f2 = __half22float2(*reinterpret_cast<__half2*>(&u.z));
    float2 f3 = __half22float2(*reinterpret_cast<__half2*>(&u.w));

    float m0v = fmaxf(fmaxf(f0.x, f0.y), fmaxf(f2.x, f2.y));
    float m1v = fmaxf(fmaxf(f1.x, f1.y), fmaxf(f3.x, f3.y));
    #pragma unroll
    for (int o = 16; o > 0; o >>= 1) {
        m0v = fmaxf(m0v, __shfl_xor_sync(0xffffffffu, m0v, o));
        m1v = fmaxf(m1v, __shfl_xor_sync(0xffffffffu, m1v, o));
    }
    if (lane == 0) { sh0[wid] = m0v; sh1[wid] = m1v; }
    __syncthreads();
    m0v = sh0[0]; m1v = sh1[0];
    #pragma unroll
    for (int i = 1; i < 8; i++) { m0v = fmaxf(m0v, sh0[i]); m1v = fmaxf(m1v, sh1[i]); }
    __syncthreads();

    const float L2E = 1.4426950408889634f;
    __half2 e0 = h2exp2(__floats2half2_rn((f0.x - m0v) * L2E, (f0.y - m0v) * L2E));
    __half2 e2 = h2exp2(__floats2half2_rn((f2.x - m0v) * L2E, (f2.y - m0v) * L2E));
    __half2 e1 = h2exp2(__floats2half2_rn((f1.x - m1v) * L2E, (f1.y - m1v) * L2E));
    __half2 e3 = h2exp2(__floats2half2_rn((f3.x - m1v) * L2E, (f3.y - m1v) * L2E));
    float2 g0 = __half22float2(e0), g1 = __half22float2(e1);
    float2 g2 = __half22float2(e2), g3 = __half22float2(e3);

    float s0 = g0.x + g0.y + g2.x + g2.y;
    float s1 = g1.x + g1.y + g3.x + g3.y;
    #pragma unroll
    for (int o = 16; o > 0; o >>= 1) {
        s0 += __shfl_xor_sync(0xffffffffu, s0, o);
        s1 += __shfl_xor_sync(0xffffffffu, s1, o);
    }
    if (lane == 0) { sh0[wid] = s0; sh1[wid] = s1; }
    __syncthreads();
    s0 = sh0[0]; s1 = sh1[0];
    #pragma unroll
    for (int i = 1; i < 8; i++) { s0 += sh0[i]; s1 += sh1[i]; }

    const float i0 = 1.0f / s0, i1 = 1.0f / s1;
    u.x = packh2(g0.x * i0, g0.y * i0);
    u.z = packh2(g2.x * i0, g2.y * i0);
    u.y = packh2(g1.x * i1, g1.y * i1);
    u.w = packh2(g3.x * i1, g3.y * i1);
    *p = u;
}

// ------------- fused residual-add + LayerNorm; writes h in A_perm16 half -------------
__global__ __launch_bounds__(256)
void ln_kernel(const __half* __restrict__ interp, const float* __restrict__ xC,
               const float* __restrict__ gamma, const float* __restrict__ beta,
               __half* __restrict__ H)
{
    __shared__ float sh[8];
    const size_t row = blockIdx.x;
    const __half* a = interp + row * DIM;
    const float* cc = xC + row * DIM;
    const int t = threadIdx.x;

    float x0 = __half2float(a[t])       + cc[t];
    float x1 = __half2float(a[t + 256]) + cc[t + 256];
    float x2 = __half2float(a[t + 512]) + cc[t + 512];

    float s = x0 + x1 + x2;
    #pragma unroll
    for (int o = 16; o > 0; o >>= 1) s += __shfl_xor_sync(0xffffffffu, s, o);
    if ((t & 31) == 0) sh[t >> 5] = s;
    __syncthreads();
    s = sh[0];
    #pragma unroll
    for (int i = 1; i < 8; i++) s += sh[i];
    const float mu = s * (1.0f / DIM);
    __syncthreads();

    float d0 = x0 - mu, d1 = x1 - mu, d2 = x2 - mu;
    float q = d0 * d0 + d1 * d1 + d2 * d2;
    #pragma unroll
    for (int o = 16; o > 0; o >>= 1) q += __shfl_xor_sync(0xffffffffu, q, o);
    if ((t & 31) == 0) sh[t >> 5] = q;
    __syncthreads();
    q = sh[0];
    #pragma unroll
    for (int i = 1; i < 8; i++) q += sh[i];

    const float rstd = rsqrtf(q * (1.0f / DIM) + 1e-5f);
    const int m = (int)row;
    const size_t rowblk = (size_t)(m >> 4) * (DIM >> 4);
    const int laneb = (m & 7) * 4;
    const int regm = (m >> 3) & 1;
    #pragma unroll
    for (int i = 0; i < 3; i++) {
        int d = t + i * 256;
        float val = (i == 0 ? d0 : i == 1 ? d1 : d2) * rstd * gamma[d] + beta[d];
        size_t off = (rowblk + (d >> 4)) * 256
                   + (size_t)(laneb + ((d & 7) >> 1)) * 8
                   + (regm + 2 * ((d & 15) >> 3)) * 2 + (d & 1);
        H[off] = __float2half_rn(val);
    }
}

// ---------------------------------- launch ----------------------------------
extern "C" void kernel_launch(void* const* d_in, const int* in_sizes, int n_in,
                              void* d_out, int out_size)
{
    const float* xA    = (const float*)d_in[0];
    const float* xB    = (const float*)d_in[1];
    const float* xC    = (const float*)d_in[2];
    const float* Wq    = (const float*)d_in[3];
    const float* bq    = (const float*)d_in[4];
    const float* Wk    = (const float*)d_in[5];
    const float* bk    = (const float*)d_in[6];
    const float* Wv    = (const float*)d_in[7];
    const float* bv    = (const float*)d_in[8];
    const float* gamma = (const float*)d_in[9];
    const float* beta  = (const float*)d_in[10];
    const float* Wfc   = (const float*)d_in[11];
    const float* bfc   = (const float*)d_in[12];
    float* out = (float*)d_out;

    __half *pxA, *pxB, *pxC, *pWq, *pWk, *pWv, *pWfc;
    __half *Q, *KA, *KB, *VA, *VB, *h, *sc1, *sc2, *interp;
    cudaGetSymbolAddress((void**)&pxA,  g_xA);
    cudaGetSymbolAddress((void**)&pxB,  g_xB);
    cudaGetSymbolAddress((void**)&pxC,  g_xC);
    cudaGetSymbolAddress((void**)&pWq,  g_Wq);
    cudaGetSymbolAddress((void**)&pWk,  g_Wk);
    cudaGetSymbolAddress((void**)&pWv,  g_Wv);
    cudaGetSymbolAddress((void**)&pWfc, g_Wfc);
    cudaGetSymbolAddress((void**)&Q,      g_Q);
    cudaGetSymbolAddress((void**)&KA,     g_KA);
    cudaGetSymbolAddress((void**)&KB,     g_KB);
    cudaGetSymbolAddress((void**)&VA,     g_VA);
    cudaGetSymbolAddress((void**)&VB,     g_VB);
    cudaGetSymbolAddress((void**)&h,      g_h);
    cudaGetSymbolAddress((void**)&sc1,    g_scores1);
    cudaGetSymbolAddress((void**)&sc2,    g_scores2);
    cudaGetSymbolAddress((void**)&interp, g_interp);

    cudaFuncSetAttribute(proj_gemm,                 cudaFuncAttributeMaxDynamicSharedMemorySize, SMEM_BYTES);
    cudaFuncSetAttribute(mma_gemm<1, false, false>, cudaFuncAttributeMaxDynamicSharedMemorySize, SMEM_BYTES);
    cudaFuncSetAttribute(mma_gemm<4, false, true >, cudaFuncAttributeMaxDynamicSharedMemorySize, SMEM_BYTES);
    cudaFuncSetAttribute(mma_gemm<0, true,  false>, cudaFuncAttributeMaxDynamicSharedMemorySize, SMEM_BYTES);

    const long sQK = (long)SEQ * DIM;    // halves
    const long sS  = (long)SEQ * SEQ;    // halves
    const float scale = 1.0f / sqrtf((float)DIM);
    const int ZBIG = 1 << 30;

    // prepass: pack fp32 -> fp16 fragment layouts
    {
        int nblkA = (ROWS >> 4) * (DIM >> 4);
        pack_A3<<<dim3(nblkA / 8, 3, 1), 256>>>(xA, xB, xC);
        int nblkB = (DIM >> 3) * (DIM >> 5);
        pack_B4<<<dim3(nblkB / 8, 4, 1), 256>>>(Wq, Wk, Wv, Wfc);
    }

    const dim3 blk(256);

    // ALL projections in one launch (z = 0..4): Q, KA, KB, VA, VB
    proj_gemm<<<dim3(DIM/BN, ROWS/BM, 5), blk, SMEM_BYTES>>>(
        pxA, pxB, pxC, pWq, pWk, pWv, bq, bk, bv, Q, KA, KB, VA, VB);

    // scores merged: z<16: Q@KA^T -> sc1 ; z>=16: Q@KB^T -> sc2 (A_perm16 out)
    mma_gemm<1, false, false><<<dim3(SEQ/BN, SEQ/BM, 32), blk, SMEM_BYTES>>>(
        Q, Q, KA, KB, nullptr, sc1, sc2, 16,
        SEQ, DIM, SEQ, sQK, sQK, sS, scale);

    // softmax (both buffers), f16x2 exp
    softmax_perm<<<BATCH * 512 * 2, 256>>>(sc1, sc2);

    // PV dual-K: interp = sc1@VA^T + sc2@VB^T (half row-major)
    mma_gemm<4, false, true><<<dim3(DIM/BN, SEQ/BM, BATCH), blk, SMEM_BYTES>>>(
        sc1, sc2, VA, VB, nullptr, interp, nullptr, ZBIG,
        DIM, SEQ, 0, sS, sQK, sQK, 1.0f);

    // residual + LN -> h (A_perm16)
    ln_kernel<<<ROWS, blk>>>(interp, xC, gamma, beta, h);

    // FC: h @ Wfc^T + bfc -> out (fp32)
    mma_gemm<0, true, false><<<dim3(DIM/BN, ROWS/BM, 1), blk, SMEM_BYTES>>>(
        h, nullptr, pWfc, nullptr, bfc, out, nullptr, ZBIG,
        DIM, DIM, 0, 0, 0, 0, 1.0f);
}